// round 12
// baseline (speedup 1.0000x reference)
#include <cuda_runtime.h>
#include <cuda_bf16.h>
#include <math.h>
#include <stdint.h>

// ---------------- Problem constants ----------------
#define B_    4
#define S_    2048
#define T_    8192          // B*S tokens
#define D_    1024          // d_model
#define DFF_  4096
#define E_    8
#define TOPK_ 2
#define CAP_  1024          // CAP_FACTOR * T / E

#define NCHK_ (T_ / 256)    // 32 dispatch chunks

// Block-split storage: value = h + l, stored as [h-block | l-block] (2K per row).
// GEMM iterates 3 phases: (A=h,B=H), (A=h,B=L), (A=l,B=H)  == exact 3-term product.

// ---------------- Device scratch (static; no allocations allowed) ----------------
__device__ __nv_bfloat16 g_xg2[(size_t)E_ * CAP_ * 2 * D_];    // 33 MB  A of GEMM1 [h|l]
__device__ __nv_bfloat16 g_w1c[(size_t)E_ * DFF_ * 2 * D_];    // 134 MB B of GEMM1 [H|L]
__device__ __nv_bfloat16 g_w2c[(size_t)E_ * D_ * 2 * DFF_];    // 134 MB B of GEMM2 [H|L]
__device__ __nv_bfloat16 g_h2 [(size_t)E_ * CAP_ * 2 * DFF_];  // 134 MB A of GEMM2 [h|l]
__device__ float g_y[(size_t)E_ * CAP_ * D_];                  // expert outputs fp32
__device__ int   g_tokens[E_ * CAP_];
__device__ float g_gates [E_ * CAP_];
__device__ int   g_te0[T_], g_te1[T_];
__device__ float g_tw0[T_], g_tw1[T_];
__device__ int   g_tslot[2 * T_];
__device__ int   g_counts[E_];
__device__ int   g_ccnt[NCHK_][E_];
__device__ int   g_cofs[NCHK_][E_];

// ---------------- helpers ----------------
#define CP_ASYNC16(sa, ga) \
    asm volatile("cp.async.cg.shared.global [%0], [%1], 16;" :: "r"(sa), "l"(ga))
#define CP_COMMIT()  asm volatile("cp.async.commit_group;")
#define SWZ(o) ((o) ^ ((((uint32_t)(o)) >> 3) & 0x70))

#define LDMATRIX_X4(f, a) \
    asm volatile("ldmatrix.sync.aligned.m8n8.x4.shared.b16 {%0,%1,%2,%3}, [%4];" \
        : "=r"((f)[0]), "=r"((f)[1]), "=r"((f)[2]), "=r"((f)[3]) : "r"(a))

#define MMA_16816(c, a, b0, b1) \
    asm volatile("mma.sync.aligned.m16n8k16.row.col.f32.bf16.bf16.f32 " \
        "{%0,%1,%2,%3}, {%4,%5,%6,%7}, {%8,%9}, {%0,%1,%2,%3};" \
        : "+f"((c)[0]), "+f"((c)[1]), "+f"((c)[2]), "+f"((c)[3]) \
        : "r"((a)[0]), "r"((a)[1]), "r"((a)[2]), "r"((a)[3]), "r"(b0), "r"(b1))

// ---------------- Router ----------------
__global__ void __launch_bounds__(256) router_kernel(
    const float* __restrict__ x, const float* __restrict__ rw)
{
    __shared__ float srw[E_ * D_];
    int tid = threadIdx.x;
    for (int i = tid; i < E_ * D_; i += 256) srw[i] = rw[i];
    __syncthreads();

    int warp = tid >> 5, lane = tid & 31;
    int t = blockIdx.x * 8 + warp;
    const float* xt = x + (size_t)t * D_;

    float acc[E_];
#pragma unroll
    for (int e = 0; e < E_; e++) acc[e] = 0.f;
    for (int c = 0; c < D_ / 32; c++) {
        float xv = xt[c * 32 + lane];
#pragma unroll
        for (int e = 0; e < E_; e++)
            acc[e] += xv * srw[e * D_ + c * 32 + lane];
    }
#pragma unroll
    for (int e = 0; e < E_; e++) {
#pragma unroll
        for (int off = 16; off; off >>= 1)
            acc[e] += __shfl_xor_sync(0xffffffffu, acc[e], off);
    }
    if (lane == 0) {
        int b0 = 0; float v0 = acc[0];
#pragma unroll
        for (int e = 1; e < E_; e++) if (acc[e] > v0) { v0 = acc[e]; b0 = e; }
        int b1 = -1; float v1 = -INFINITY;
#pragma unroll
        for (int e = 0; e < E_; e++) if (e != b0 && acc[e] > v1) { v1 = acc[e]; b1 = e; }
        float ex = expf(v1 - v0);
        float w0 = 1.f / (1.f + ex);
        float w1 = ex * w0;
        g_te0[t] = b0; g_te1[t] = b1;
        g_tw0[t] = w0; g_tw1[t] = w1;
        g_tslot[2 * t + 0] = -1;
        g_tslot[2 * t + 1] = -1;
    }
}

// ---------------- Dispatch phase A: per-chunk per-expert counts ----------------
__global__ void __launch_bounds__(256) count_kernel()
{
    int tid = threadIdx.x;
    int t = blockIdx.x * 256 + tid;
    int lane = tid & 31, warp = tid >> 5;
    int e0 = g_te0[t], e1 = g_te1[t];
    __shared__ int wcnt[8][E_];
#pragma unroll
    for (int e = 0; e < E_; e++) {
        unsigned b = __ballot_sync(0xffffffffu, (e0 == e) || (e1 == e));
        if (lane == 0) wcnt[warp][e] = __popc(b);
    }
    __syncthreads();
    if (tid < E_) {
        int s = 0;
#pragma unroll
        for (int w = 0; w < 8; w++) s += wcnt[w][tid];
        g_ccnt[blockIdx.x][tid] = s;
    }
}

// ---------------- Dispatch phase B: chunk scan + pad-slot init ----------------
__global__ void __launch_bounds__(256) scan_init_kernel()
{
    int tid = threadIdx.x;
    for (int i = tid; i < E_ * CAP_; i += 256) { g_tokens[i] = 0; g_gates[i] = 0.f; }
    if (tid < E_) {
        int run = 0;
#pragma unroll
        for (int b = 0; b < NCHK_; b++) {
            g_cofs[b][tid] = run;
            run += g_ccnt[b][tid];
        }
        g_counts[tid] = run;
    }
}

// ---------------- Dispatch phase C: place tokens (token-order ranks) ----------------
__global__ void __launch_bounds__(256) place_kernel()
{
    int tid = threadIdx.x;
    int t = blockIdx.x * 256 + tid;
    int lane = tid & 31, warp = tid >> 5;
    int e0 = g_te0[t], e1 = g_te1[t];
    unsigned lt = (lane == 0) ? 0u : (0xffffffffu >> (32 - lane));
    __shared__ int ws[8];

#pragma unroll
    for (int e = 0; e < E_; e++) {
        bool f0 = (e0 == e), f1 = (e1 == e);
        bool f = f0 || f1;
        unsigned b = __ballot_sync(0xffffffffu, f);
        if (lane == 0) ws[warp] = __popc(b);
        __syncthreads();
        if (f) {
            int wpre = 0;
#pragma unroll
            for (int w = 0; w < 8; w++) if (w < warp) wpre += ws[w];
            int rank = wpre + __popc(b & lt);
            int slot = g_cofs[blockIdx.x][e] + rank;
            if (slot < CAP_) {
                g_tokens[e * CAP_ + slot] = t;
                g_gates [e * CAP_ + slot] = f0 ? g_tw0[t] : g_tw1[t];
                g_tslot[2 * t + (f0 ? 0 : 1)] = e * CAP_ + slot;
            }
        }
        __syncthreads();
    }
}

// ---------------- Gather + 2-block bf16 split: row = [h(D) | l(D)] ----------------
__global__ void __launch_bounds__(256) gather_split_kernel(const float* __restrict__ x)
{
    int row = blockIdx.x;                       // e*CAP + c
    int t = g_tokens[row];
    int tid = threadIdx.x;
    float4 v = ((const float4*)(x + (size_t)t * D_))[tid];
    float vv[4] = {v.x, v.y, v.z, v.w};
    unsigned short hs[4], ls[4];
#pragma unroll
    for (int j = 0; j < 4; j++) {
        __nv_bfloat16 hb = __float2bfloat16_rn(vv[j]);
        __nv_bfloat16 lb = __float2bfloat16_rn(vv[j] - __bfloat162float(hb));
        hs[j] = __bfloat16_as_ushort(hb);
        ls[j] = __bfloat16_as_ushort(lb);
    }
    __nv_bfloat16* base = g_xg2 + (size_t)row * 2 * D_;
    uint2 hv, lv;
    hv.x = (uint32_t)hs[0] | ((uint32_t)hs[1] << 16);
    hv.y = (uint32_t)hs[2] | ((uint32_t)hs[3] << 16);
    lv.x = (uint32_t)ls[0] | ((uint32_t)ls[1] << 16);
    lv.y = (uint32_t)ls[2] | ((uint32_t)ls[3] << 16);
    *(uint2*)(base + 4 * tid)      = hv;
    *(uint2*)(base + D_ + 4 * tid) = lv;
}

// ---------------- Weight transpose + split: [E,K,N] fp32 -> [E,N,2K] bf16 [H|L] ----------------
__global__ void __launch_bounds__(256) convert_w_kernel(
    const float* __restrict__ src, __nv_bfloat16* __restrict__ dst, int K, int N)
{
    __shared__ float tile[32][129];
    int e = blockIdx.z;
    int k0 = blockIdx.y * 32, n0 = blockIdx.x * 128;
    int tid = threadIdx.x;
    const float* se = src + (size_t)e * K * N;
    __nv_bfloat16* de = dst + (size_t)e * N * 2 * K;

#pragma unroll
    for (int j = 0; j < 4; j++) {
        int idx = tid + j * 256;
        int r = idx >> 5, c4 = idx & 31;
        float4 v = *(const float4*)&se[(size_t)(k0 + r) * N + n0 + c4 * 4];
        float* tr = &tile[r][c4 * 4];
        tr[0] = v.x; tr[1] = v.y; tr[2] = v.z; tr[3] = v.w;
    }
    __syncthreads();

#pragma unroll
    for (int j = 0; j < 8; j++) {
        int task = tid + j * 256;
        int kp = task & 15;               // k-pair 0..15
        int nl = task >> 4;               // n 0..127
        int n = n0 + nl;
        float v0 = tile[2 * kp][nl];
        float v1 = tile[2 * kp + 1][nl];
        __nv_bfloat16 h0b = __float2bfloat16_rn(v0);
        __nv_bfloat16 l0b = __float2bfloat16_rn(v0 - __bfloat162float(h0b));
        __nv_bfloat16 h1b = __float2bfloat16_rn(v1);
        __nv_bfloat16 l1b = __float2bfloat16_rn(v1 - __bfloat162float(h1b));
        uint32_t h0 = __bfloat16_as_ushort(h0b), l0 = __bfloat16_as_ushort(l0b);
        uint32_t h1 = __bfloat16_as_ushort(h1b), l1 = __bfloat16_as_ushort(l1b);
        __nv_bfloat16* rowp = de + (size_t)n * 2 * K;
        *(uint32_t*)(rowp + (k0 + 2 * kp))     = h0 | (h1 << 16);   // H block
        *(uint32_t*)(rowp + K + (k0 + 2 * kp)) = l0 | (l1 << 16);   // L block
    }
}

// ---------------- HMMA grouped GEMM with 3-phase block split (per-expert) ----------------
// A: [M, 2*Ks] bf16 = [h|l]; B: [Nt, 2*Ks] bf16 = [H|L]. Pointers pre-offset per expert.
__device__ __forceinline__ float gelu_exact(float v) {
    return 0.5f * v * (1.f + erff(v * 0.70710678118654752f));
}

#define SMEM_BYTES_GEMM (192 * 1024)

template<int BN, int NSTAGE, int PF, bool GELU_SPLIT>
__global__ void __launch_bounds__(256, 1) gemm_mma_kernel(
    const __nv_bfloat16* __restrict__ A, const __nv_bfloat16* __restrict__ Bw,
    const float* __restrict__ be, void* __restrict__ outv,
    int M, int Nt, int Ks)
{
    constexpr int ABYTES = 128 * 128;
    constexpr int BBYTES = BN * 128;
    constexpr int STAGE  = ABYTES + BBYTES;
    constexpr int WCOLS  = BN / 4;
    constexpr int N8     = WCOLS / 8;
    constexpr int NTB    = (WCOLS + 15) / 16;

    extern __shared__ char smem[];
    uint32_t sb = (uint32_t)__cvta_generic_to_shared(smem);

    int tid  = threadIdx.x;
    int lane = tid & 31;
    int warp = tid >> 5;
    int wm = warp >> 2, wn = warp & 3;

    int n0 = blockIdx.x * BN, m0 = blockIdx.y * 128;

    const int KC  = Ks >> 6;                    // 64-col chunks per block
    const int NCH = 3 * KC;                     // 3 phases
    const size_t ld = (size_t)Ks * 4;           // row stride bytes (2*Ks bf16)

    const char* Ae = (const char*)(A  + (size_t)m0 * 2 * Ks);
    const char* Be = (const char*)(Bw + (size_t)n0 * 2 * Ks);

    auto chunk_off = [&](int c, int& aB, int& bB) {
        int phase = c / KC, idx = c - phase * KC;
        aB = ((phase == 2 ? KC + idx : idx)) * 128;   // l for phase 2, else h
        bB = ((phase == 1 ? KC + idx : idx)) * 128;   // L for phase 1, else H
    };

    auto load_stage = [&](int c, int s) {
        int aB, bB; chunk_off(c, aB, bB);
        const char* Ag = Ae + aB;
        const char* Bg = Be + bB;
        uint32_t Aoff = sb + s * STAGE;
        uint32_t Boff = Aoff + ABYTES;
#pragma unroll
        for (int i = 0; i < 4; i++) {
            int idx = tid + i * 256;
            int r = idx >> 3, c16 = idx & 7;
            CP_ASYNC16(Aoff + SWZ(r * 128 + c16 * 16), Ag + (size_t)r * ld + c16 * 16);
        }
#pragma unroll
        for (int i = 0; i < BN / 32; i++) {
            int idx = tid + i * 256;
            int r = idx >> 3, c16 = idx & 7;
            CP_ASYNC16(Boff + SWZ(r * 128 + c16 * 16), Bg + (size_t)r * ld + c16 * 16);
        }
    };

    float acc[4][N8][4];
#pragma unroll
    for (int i = 0; i < 4; i++)
#pragma unroll
        for (int j = 0; j < N8; j++)
#pragma unroll
            for (int k = 0; k < 4; k++) acc[i][j][k] = 0.f;

#pragma unroll
    for (int p = 0; p < PF; p++) { load_stage(p, p); CP_COMMIT(); }

    int aRow = wm * 64 + (lane & 15);
    int bRow = wn * WCOLS + (lane & 15);
    int halfCol = (lane >> 4) * 16;

    for (int c = 0; c < NCH; ++c) {
        asm volatile("cp.async.wait_group %0;" :: "n"(PF - 1));
        __syncthreads();
        if (c + PF < NCH) load_stage(c + PF, (c + PF) % NSTAGE);
        CP_COMMIT();

        int s = c % NSTAGE;
        uint32_t Aoff = sb + s * STAGE;
        uint32_t Boff = Aoff + ABYTES;

#pragma unroll
        for (int ks = 0; ks < 4; ks++) {
            uint32_t afr[4][4], bfr[NTB][4];
#pragma unroll
            for (int mt = 0; mt < 4; mt++) {
                uint32_t ad = Aoff + SWZ((aRow + mt * 16) * 128 + ks * 32 + halfCol);
                LDMATRIX_X4(afr[mt], ad);
            }
#pragma unroll
            for (int nt = 0; nt < NTB; nt++) {
                uint32_t bd = Boff + SWZ((bRow + nt * 16) * 128 + ks * 32 + halfCol);
                LDMATRIX_X4(bfr[nt], bd);
            }
#pragma unroll
            for (int mt = 0; mt < 4; mt++)
#pragma unroll
                for (int n8 = 0; n8 < N8; n8++) {
                    int nt = n8 >> 1, j = n8 & 1;
                    MMA_16816(acc[mt][n8], afr[mt], bfr[nt][j], bfr[nt][2 + j]);
                }
        }
    }

    // -------- Epilogue --------
#pragma unroll
    for (int mt = 0; mt < 4; mt++) {
#pragma unroll
        for (int rr = 0; rr < 2; rr++) {
            int row = m0 + wm * 64 + mt * 16 + (lane >> 2) + rr * 8;
#pragma unroll
            for (int n8 = 0; n8 < N8; n8++) {
                int colL = wn * WCOLS + n8 * 8 + (lane & 3) * 2;
                int col  = n0 + colL;
                float v0 = acc[mt][n8][rr * 2 + 0] + be[col];
                float v1 = acc[mt][n8][rr * 2 + 1] + be[col + 1];
                if (GELU_SPLIT) {
                    v0 = gelu_exact(v0); v1 = gelu_exact(v1);
                    __nv_bfloat16 h0b = __float2bfloat16_rn(v0);
                    __nv_bfloat16 l0b = __float2bfloat16_rn(v0 - __bfloat162float(h0b));
                    __nv_bfloat16 h1b = __float2bfloat16_rn(v1);
                    __nv_bfloat16 l1b = __float2bfloat16_rn(v1 - __bfloat162float(h1b));
                    uint32_t h0 = __bfloat16_as_ushort(h0b), l0 = __bfloat16_as_ushort(l0b);
                    uint32_t h1 = __bfloat16_as_ushort(h1b), l1 = __bfloat16_as_ushort(l1b);
                    __nv_bfloat16* rowp = (__nv_bfloat16*)outv + (size_t)row * 2 * Nt;
                    *(uint32_t*)(rowp + col)      = h0 | (h1 << 16);   // h block
                    *(uint32_t*)(rowp + Nt + col) = l0 | (l1 << 16);   // l block
                } else {
                    float* oe = (float*)outv + (size_t)row * Nt + col;
                    *(float2*)oe = make_float2(v0, v1);
                }
            }
        }
    }
}

// ---------------- Combine ----------------
__global__ void __launch_bounds__(256) combine_kernel(float* __restrict__ out)
{
    int t = blockIdx.x;
    int p0 = g_tslot[2 * t], p1 = g_tslot[2 * t + 1];
    int i = threadIdx.x;
    float4 r = make_float4(0.f, 0.f, 0.f, 0.f);
    if (p0 >= 0) {
        float w = g_gates[p0];
        float4 a = ((const float4*)(g_y + (size_t)p0 * D_))[i];
        r.x += w * a.x; r.y += w * a.y; r.z += w * a.z; r.w += w * a.w;
    }
    if (p1 >= 0) {
        float w = g_gates[p1];
        float4 a = ((const float4*)(g_y + (size_t)p1 * D_))[i];
        r.x += w * a.x; r.y += w * a.y; r.z += w * a.z; r.w += w * a.w;
    }
    ((float4*)(out + (size_t)t * D_))[i] = r;
}

// ---------------- Load-balancing loss ----------------
__global__ void loss_kernel(float* __restrict__ loss_out)
{
    if (threadIdx.x == 0) {
        const float ideal = (float)T_ * TOPK_ / E_;
        float s = 0.f;
#pragma unroll
        for (int e = 0; e < E_; e++) {
            float d = (float)g_counts[e] - ideal;
            s += d * d;
        }
        *loss_out = s / ((float)T_ * (float)T_);
    }
}

// ---------------- Launch ----------------
extern "C" void kernel_launch(void* const* d_in, const int* in_sizes, int n_in,
                              void* d_out, int out_size)
{
    const float* x  = (const float*)d_in[0];
    const float* rw = (const float*)d_in[1];
    const float* w1 = (const float*)d_in[2];
    const float* b1 = (const float*)d_in[3];
    const float* w2 = (const float*)d_in[4];
    const float* b2 = (const float*)d_in[5];
    float* out = (float*)d_out;

    __nv_bfloat16 *xg2, *w1c, *w2c, *h2; float* y;
    cudaGetSymbolAddress((void**)&xg2, g_xg2);
    cudaGetSymbolAddress((void**)&w1c, g_w1c);
    cudaGetSymbolAddress((void**)&w2c, g_w2c);
    cudaGetSymbolAddress((void**)&h2,  g_h2);
    cudaGetSymbolAddress((void**)&y,   g_y);

    cudaFuncSetAttribute((const void*)gemm_mma_kernel<256, 4, 3, true>,
                         cudaFuncAttributeMaxDynamicSharedMemorySize, SMEM_BYTES_GEMM);
    cudaFuncSetAttribute((const void*)gemm_mma_kernel<256, 4, 3, false>,
                         cudaFuncAttributeMaxDynamicSharedMemorySize, SMEM_BYTES_GEMM);

    // ONE side stream (proven safe in R8-R10) + lightweight events only.
    cudaStream_t sw;
    cudaEvent_t evRoot, evW1, evG1[E_], evEnd;
    cudaStreamCreateWithFlags(&sw, cudaStreamNonBlocking);
    cudaEventCreateWithFlags(&evRoot, cudaEventDisableTiming);
    cudaEventCreateWithFlags(&evW1, cudaEventDisableTiming);
    cudaEventCreateWithFlags(&evEnd, cudaEventDisableTiming);
    for (int e = 0; e < E_; e++) cudaEventCreateWithFlags(&evG1[e], cudaEventDisableTiming);

    cudaEventRecord(evRoot, 0);
    cudaStreamWaitEvent(sw, evRoot, 0);

    // Side stream: weight conversions (in order). GEMM2_e launches later on sw
    // are automatically ordered after conv_w2.
    convert_w_kernel<<<dim3(DFF_ / 128, D_ / 32, E_), 256, 0, sw>>>(w1, w1c, D_, DFF_);
    cudaEventRecord(evW1, sw);
    convert_w_kernel<<<dim3(D_ / 128, DFF_ / 32, E_), 256, 0, sw>>>(w2, w2c, DFF_, D_);

    // Main stream: routing chain + gather
    router_kernel<<<T_ / 8, 256>>>(x, rw);
    count_kernel<<<NCHK_, 256>>>();
    scan_init_kernel<<<1, 256>>>();
    place_kernel<<<NCHK_, 256>>>();
    gather_split_kernel<<<E_ * CAP_, 256>>>(x);

    // GEMM1 needs conv_w1
    cudaStreamWaitEvent(0, evW1, 0);

    // Per-expert chaining: GEMM1_e on main; GEMM2_e on sw gated by evG1[e].
    for (int e = 0; e < E_; e++) {
        gemm_mma_kernel<256, 4, 3, true>
            <<<dim3(DFF_ / 256, CAP_ / 128), 256, SMEM_BYTES_GEMM>>>(
            xg2 + (size_t)e * CAP_ * 2 * D_,
            w1c + (size_t)e * DFF_ * 2 * D_,
            b1 + (size_t)e * DFF_,
            (void*)(h2 + (size_t)e * CAP_ * 2 * DFF_),
            CAP_, DFF_, D_);
        cudaEventRecord(evG1[e], 0);

        cudaStreamWaitEvent(sw, evG1[e], 0);
        gemm_mma_kernel<256, 4, 3, false>
            <<<dim3(D_ / 256, CAP_ / 128), 256, SMEM_BYTES_GEMM, sw>>>(
            h2 + (size_t)e * CAP_ * 2 * DFF_,
            w2c + (size_t)e * D_ * 2 * DFF_,
            b2 + (size_t)e * D_,
            (void*)(y + (size_t)e * CAP_ * D_),
            CAP_, D_, DFF_);
    }
    cudaEventRecord(evEnd, sw);

    // Join, then combine + loss on main stream
    cudaStreamWaitEvent(0, evEnd, 0);
    combine_kernel<<<T_, 256>>>(out);
    loss_kernel<<<1, 32>>>(out + (out_size - 1));
}

// round 13
// speedup vs baseline: 2.0596x; 2.0596x over previous
#include <cuda_runtime.h>
#include <cuda_bf16.h>
#include <math.h>
#include <stdint.h>

// ---------------- Problem constants ----------------
#define B_    4
#define S_    2048
#define T_    8192          // B*S tokens
#define D_    1024          // d_model
#define DFF_  4096
#define E_    8
#define TOPK_ 2
#define CAP_  1024          // CAP_FACTOR * T / E

#define NCHK_ (T_ / 256)    // 32 dispatch chunks

// Block-split storage: value = h + l, stored as [h-block | l-block] (2K per row).
// GEMM iterates 3 phases: (A=h,B=H), (A=h,B=L), (A=l,B=H)  == exact 3-term product.

// ---------------- Device scratch (static; no allocations allowed) ----------------
__device__ __nv_bfloat16 g_xg2[(size_t)E_ * CAP_ * 2 * D_];    // 33 MB  A of GEMM1 [h|l]
__device__ __nv_bfloat16 g_w1c[(size_t)E_ * DFF_ * 2 * D_];    // 134 MB B of GEMM1 [H|L]
__device__ __nv_bfloat16 g_w2c[(size_t)E_ * D_ * 2 * DFF_];    // 134 MB B of GEMM2 [H|L]
__device__ __nv_bfloat16 g_h2 [(size_t)E_ * CAP_ * 2 * DFF_];  // 134 MB A of GEMM2 [h|l]
__device__ float g_y[(size_t)E_ * CAP_ * D_];                  // expert outputs fp32
__device__ int   g_tokens[E_ * CAP_];
__device__ float g_gates [E_ * CAP_];
__device__ int   g_te0[T_], g_te1[T_];
__device__ float g_tw0[T_], g_tw1[T_];
__device__ int   g_tslot[2 * T_];
__device__ int   g_counts[E_];
__device__ int   g_ccnt[NCHK_][E_];
__device__ int   g_cofs[NCHK_][E_];

// ---------------- helpers ----------------
#define CP_ASYNC16(sa, ga) \
    asm volatile("cp.async.cg.shared.global [%0], [%1], 16;" :: "r"(sa), "l"(ga))
#define CP_COMMIT()  asm volatile("cp.async.commit_group;")
#define SWZ(o) ((o) ^ ((((uint32_t)(o)) >> 3) & 0x70))

#define LDMATRIX_X4(f, a) \
    asm volatile("ldmatrix.sync.aligned.m8n8.x4.shared.b16 {%0,%1,%2,%3}, [%4];" \
        : "=r"((f)[0]), "=r"((f)[1]), "=r"((f)[2]), "=r"((f)[3]) : "r"(a))

#define MMA_16816(c, a, b0, b1) \
    asm volatile("mma.sync.aligned.m16n8k16.row.col.f32.bf16.bf16.f32 " \
        "{%0,%1,%2,%3}, {%4,%5,%6,%7}, {%8,%9}, {%0,%1,%2,%3};" \
        : "+f"((c)[0]), "+f"((c)[1]), "+f"((c)[2]), "+f"((c)[3]) \
        : "r"((a)[0]), "r"((a)[1]), "r"((a)[2]), "r"((a)[3]), "r"(b0), "r"(b1))

// ---------------- Router ----------------
__global__ void __launch_bounds__(256) router_kernel(
    const float* __restrict__ x, const float* __restrict__ rw)
{
    __shared__ float srw[E_ * D_];
    int tid = threadIdx.x;
    for (int i = tid; i < E_ * D_; i += 256) srw[i] = rw[i];
    __syncthreads();

    int warp = tid >> 5, lane = tid & 31;
    int t = blockIdx.x * 8 + warp;
    const float* xt = x + (size_t)t * D_;

    float acc[E_];
#pragma unroll
    for (int e = 0; e < E_; e++) acc[e] = 0.f;
    for (int c = 0; c < D_ / 32; c++) {
        float xv = xt[c * 32 + lane];
#pragma unroll
        for (int e = 0; e < E_; e++)
            acc[e] += xv * srw[e * D_ + c * 32 + lane];
    }
#pragma unroll
    for (int e = 0; e < E_; e++) {
#pragma unroll
        for (int off = 16; off; off >>= 1)
            acc[e] += __shfl_xor_sync(0xffffffffu, acc[e], off);
    }
    if (lane == 0) {
        int b0 = 0; float v0 = acc[0];
#pragma unroll
        for (int e = 1; e < E_; e++) if (acc[e] > v0) { v0 = acc[e]; b0 = e; }
        int b1 = -1; float v1 = -INFINITY;
#pragma unroll
        for (int e = 0; e < E_; e++) if (e != b0 && acc[e] > v1) { v1 = acc[e]; b1 = e; }
        float ex = expf(v1 - v0);
        float w0 = 1.f / (1.f + ex);
        float w1 = ex * w0;
        g_te0[t] = b0; g_te1[t] = b1;
        g_tw0[t] = w0; g_tw1[t] = w1;
        g_tslot[2 * t + 0] = -1;
        g_tslot[2 * t + 1] = -1;
    }
}

// ---------------- Dispatch phase A: per-chunk per-expert counts ----------------
__global__ void __launch_bounds__(256) count_kernel()
{
    int tid = threadIdx.x;
    int t = blockIdx.x * 256 + tid;
    int lane = tid & 31, warp = tid >> 5;
    int e0 = g_te0[t], e1 = g_te1[t];
    __shared__ int wcnt[8][E_];
#pragma unroll
    for (int e = 0; e < E_; e++) {
        unsigned b = __ballot_sync(0xffffffffu, (e0 == e) || (e1 == e));
        if (lane == 0) wcnt[warp][e] = __popc(b);
    }
    __syncthreads();
    if (tid < E_) {
        int s = 0;
#pragma unroll
        for (int w = 0; w < 8; w++) s += wcnt[w][tid];
        g_ccnt[blockIdx.x][tid] = s;
    }
}

// ---------------- Dispatch phase B: chunk scan + pad-slot init ----------------
__global__ void __launch_bounds__(256) scan_init_kernel()
{
    int tid = threadIdx.x;
    for (int i = tid; i < E_ * CAP_; i += 256) { g_tokens[i] = 0; g_gates[i] = 0.f; }
    if (tid < E_) {
        int run = 0;
#pragma unroll
        for (int b = 0; b < NCHK_; b++) {
            g_cofs[b][tid] = run;
            run += g_ccnt[b][tid];
        }
        g_counts[tid] = run;
    }
}

// ---------------- Dispatch phase C: place tokens (token-order ranks) ----------------
__global__ void __launch_bounds__(256) place_kernel()
{
    int tid = threadIdx.x;
    int t = blockIdx.x * 256 + tid;
    int lane = tid & 31, warp = tid >> 5;
    int e0 = g_te0[t], e1 = g_te1[t];
    unsigned lt = (lane == 0) ? 0u : (0xffffffffu >> (32 - lane));
    __shared__ int ws[8];

#pragma unroll
    for (int e = 0; e < E_; e++) {
        bool f0 = (e0 == e), f1 = (e1 == e);
        bool f = f0 || f1;
        unsigned b = __ballot_sync(0xffffffffu, f);
        if (lane == 0) ws[warp] = __popc(b);
        __syncthreads();
        if (f) {
            int wpre = 0;
#pragma unroll
            for (int w = 0; w < 8; w++) if (w < warp) wpre += ws[w];
            int rank = wpre + __popc(b & lt);
            int slot = g_cofs[blockIdx.x][e] + rank;
            if (slot < CAP_) {
                g_tokens[e * CAP_ + slot] = t;
                g_gates [e * CAP_ + slot] = f0 ? g_tw0[t] : g_tw1[t];
                g_tslot[2 * t + (f0 ? 0 : 1)] = e * CAP_ + slot;
            }
        }
        __syncthreads();
    }
}

// ---------------- Gather + 2-block bf16 split: row = [h(D) | l(D)] ----------------
__global__ void __launch_bounds__(256) gather_split_kernel(const float* __restrict__ x)
{
    int row = blockIdx.x;                       // e*CAP + c
    int t = g_tokens[row];
    int tid = threadIdx.x;
    float4 v = ((const float4*)(x + (size_t)t * D_))[tid];
    float vv[4] = {v.x, v.y, v.z, v.w};
    unsigned short hs[4], ls[4];
#pragma unroll
    for (int j = 0; j < 4; j++) {
        __nv_bfloat16 hb = __float2bfloat16_rn(vv[j]);
        __nv_bfloat16 lb = __float2bfloat16_rn(vv[j] - __bfloat162float(hb));
        hs[j] = __bfloat16_as_ushort(hb);
        ls[j] = __bfloat16_as_ushort(lb);
    }
    __nv_bfloat16* base = g_xg2 + (size_t)row * 2 * D_;
    uint2 hv, lv;
    hv.x = (uint32_t)hs[0] | ((uint32_t)hs[1] << 16);
    hv.y = (uint32_t)hs[2] | ((uint32_t)hs[3] << 16);
    lv.x = (uint32_t)ls[0] | ((uint32_t)ls[1] << 16);
    lv.y = (uint32_t)ls[2] | ((uint32_t)ls[3] << 16);
    *(uint2*)(base + 4 * tid)      = hv;
    *(uint2*)(base + D_ + 4 * tid) = lv;
}

// ---------------- Weight transpose + split: [E,K,N] fp32 -> [E,N,2K] bf16 [H|L] ----------------
__global__ void __launch_bounds__(256) convert_w_kernel(
    const float* __restrict__ src, __nv_bfloat16* __restrict__ dst, int K, int N)
{
    __shared__ float tile[32][129];
    int e = blockIdx.z;
    int k0 = blockIdx.y * 32, n0 = blockIdx.x * 128;
    int tid = threadIdx.x;
    const float* se = src + (size_t)e * K * N;
    __nv_bfloat16* de = dst + (size_t)e * N * 2 * K;

#pragma unroll
    for (int j = 0; j < 4; j++) {
        int idx = tid + j * 256;
        int r = idx >> 5, c4 = idx & 31;
        float4 v = *(const float4*)&se[(size_t)(k0 + r) * N + n0 + c4 * 4];
        float* tr = &tile[r][c4 * 4];
        tr[0] = v.x; tr[1] = v.y; tr[2] = v.z; tr[3] = v.w;
    }
    __syncthreads();

#pragma unroll
    for (int j = 0; j < 8; j++) {
        int task = tid + j * 256;
        int kp = task & 15;               // k-pair 0..15
        int nl = task >> 4;               // n 0..127
        int n = n0 + nl;
        float v0 = tile[2 * kp][nl];
        float v1 = tile[2 * kp + 1][nl];
        __nv_bfloat16 h0b = __float2bfloat16_rn(v0);
        __nv_bfloat16 l0b = __float2bfloat16_rn(v0 - __bfloat162float(h0b));
        __nv_bfloat16 h1b = __float2bfloat16_rn(v1);
        __nv_bfloat16 l1b = __float2bfloat16_rn(v1 - __bfloat162float(h1b));
        uint32_t h0 = __bfloat16_as_ushort(h0b), l0 = __bfloat16_as_ushort(l0b);
        uint32_t h1 = __bfloat16_as_ushort(h1b), l1 = __bfloat16_as_ushort(l1b);
        __nv_bfloat16* rowp = de + (size_t)n * 2 * K;
        *(uint32_t*)(rowp + (k0 + 2 * kp))     = h0 | (h1 << 16);   // H block
        *(uint32_t*)(rowp + K + (k0 + 2 * kp)) = l0 | (l1 << 16);   // L block
    }
}

// ---------------- HMMA grouped GEMM with 3-phase block split ----------------
// A: [M, 2*Ks] bf16 = [h|l]; B: [Nt, 2*Ks] bf16 = [H|L]. Batched over experts (z).
__device__ __forceinline__ float gelu_exact(float v) {
    return 0.5f * v * (1.f + erff(v * 0.70710678118654752f));
}

#define SMEM_BYTES_GEMM (192 * 1024)

template<int BN, int NSTAGE, int PF, bool GELU_SPLIT>
__global__ void __launch_bounds__(256, 1) gemm_mma_kernel(
    const __nv_bfloat16* __restrict__ A, const __nv_bfloat16* __restrict__ Bw,
    const float* __restrict__ bias, void* __restrict__ outv,
    int M, int Nt, int Ks)
{
    constexpr int ABYTES = 128 * 128;
    constexpr int BBYTES = BN * 128;
    constexpr int STAGE  = ABYTES + BBYTES;
    constexpr int WCOLS  = BN / 4;
    constexpr int N8     = WCOLS / 8;
    constexpr int NTB    = (WCOLS + 15) / 16;

    extern __shared__ char smem[];
    uint32_t sb = (uint32_t)__cvta_generic_to_shared(smem);

    int tid  = threadIdx.x;
    int lane = tid & 31;
    int warp = tid >> 5;
    int wm = warp >> 2, wn = warp & 3;

    int e  = blockIdx.z;
    int n0 = blockIdx.x * BN, m0 = blockIdx.y * 128;

    const int KC  = Ks >> 6;                    // 64-col chunks per block
    const int NCH = 3 * KC;                     // 3 phases
    const size_t ld = (size_t)Ks * 4;           // row stride bytes (2*Ks bf16)

    const char* Ae = (const char*)(A  + (size_t)e * M  * 2 * Ks + (size_t)m0 * 2 * Ks);
    const char* Be = (const char*)(Bw + (size_t)e * Nt * 2 * Ks + (size_t)n0 * 2 * Ks);
    const float* be = bias + (size_t)e * Nt;

    auto chunk_off = [&](int c, int& aB, int& bB) {
        int phase = c / KC, idx = c - phase * KC;
        aB = ((phase == 2 ? KC + idx : idx)) * 128;   // l for phase 2, else h
        bB = ((phase == 1 ? KC + idx : idx)) * 128;   // L for phase 1, else H
    };

    auto load_stage = [&](int c, int s) {
        int aB, bB; chunk_off(c, aB, bB);
        const char* Ag = Ae + aB;
        const char* Bg = Be + bB;
        uint32_t Aoff = sb + s * STAGE;
        uint32_t Boff = Aoff + ABYTES;
#pragma unroll
        for (int i = 0; i < 4; i++) {
            int idx = tid + i * 256;
            int r = idx >> 3, c16 = idx & 7;
            CP_ASYNC16(Aoff + SWZ(r * 128 + c16 * 16), Ag + (size_t)r * ld + c16 * 16);
        }
#pragma unroll
        for (int i = 0; i < BN / 32; i++) {
            int idx = tid + i * 256;
            int r = idx >> 3, c16 = idx & 7;
            CP_ASYNC16(Boff + SWZ(r * 128 + c16 * 16), Bg + (size_t)r * ld + c16 * 16);
        }
    };

    float acc[4][N8][4];
#pragma unroll
    for (int i = 0; i < 4; i++)
#pragma unroll
        for (int j = 0; j < N8; j++)
#pragma unroll
            for (int k = 0; k < 4; k++) acc[i][j][k] = 0.f;

#pragma unroll
    for (int p = 0; p < PF; p++) { load_stage(p, p); CP_COMMIT(); }

    int aRow = wm * 64 + (lane & 15);
    int bRow = wn * WCOLS + (lane & 15);
    int halfCol = (lane >> 4) * 16;

    for (int c = 0; c < NCH; ++c) {
        asm volatile("cp.async.wait_group %0;" :: "n"(PF - 1));
        __syncthreads();
        if (c + PF < NCH) load_stage(c + PF, (c + PF) % NSTAGE);
        CP_COMMIT();

        int s = c % NSTAGE;
        uint32_t Aoff = sb + s * STAGE;
        uint32_t Boff = Aoff + ABYTES;

#pragma unroll
        for (int ks = 0; ks < 4; ks++) {
            uint32_t afr[4][4], bfr[NTB][4];
#pragma unroll
            for (int mt = 0; mt < 4; mt++) {
                uint32_t ad = Aoff + SWZ((aRow + mt * 16) * 128 + ks * 32 + halfCol);
                LDMATRIX_X4(afr[mt], ad);
            }
#pragma unroll
            for (int nt = 0; nt < NTB; nt++) {
                uint32_t bd = Boff + SWZ((bRow + nt * 16) * 128 + ks * 32 + halfCol);
                LDMATRIX_X4(bfr[nt], bd);
            }
#pragma unroll
            for (int mt = 0; mt < 4; mt++)
#pragma unroll
                for (int n8 = 0; n8 < N8; n8++) {
                    int nt = n8 >> 1, j = n8 & 1;
                    MMA_16816(acc[mt][n8], afr[mt], bfr[nt][j], bfr[nt][2 + j]);
                }
        }
    }

    // -------- Epilogue --------
#pragma unroll
    for (int mt = 0; mt < 4; mt++) {
#pragma unroll
        for (int rr = 0; rr < 2; rr++) {
            int row = m0 + wm * 64 + mt * 16 + (lane >> 2) + rr * 8;
#pragma unroll
            for (int n8 = 0; n8 < N8; n8++) {
                int colL = wn * WCOLS + n8 * 8 + (lane & 3) * 2;
                int col  = n0 + colL;
                float v0 = acc[mt][n8][rr * 2 + 0] + be[col];
                float v1 = acc[mt][n8][rr * 2 + 1] + be[col + 1];
                if (GELU_SPLIT) {
                    v0 = gelu_exact(v0); v1 = gelu_exact(v1);
                    __nv_bfloat16 h0b = __float2bfloat16_rn(v0);
                    __nv_bfloat16 l0b = __float2bfloat16_rn(v0 - __bfloat162float(h0b));
                    __nv_bfloat16 h1b = __float2bfloat16_rn(v1);
                    __nv_bfloat16 l1b = __float2bfloat16_rn(v1 - __bfloat162float(h1b));
                    uint32_t h0 = __bfloat16_as_ushort(h0b), l0 = __bfloat16_as_ushort(l0b);
                    uint32_t h1 = __bfloat16_as_ushort(h1b), l1 = __bfloat16_as_ushort(l1b);
                    __nv_bfloat16* rowp = (__nv_bfloat16*)outv
                        + (size_t)e * M * 2 * Nt + (size_t)row * 2 * Nt;
                    *(uint32_t*)(rowp + col)      = h0 | (h1 << 16);   // h block
                    *(uint32_t*)(rowp + Nt + col) = l0 | (l1 << 16);   // l block
                } else {
                    float* oe = (float*)outv + (size_t)e * M * Nt + (size_t)row * Nt + col;
                    *(float2*)oe = make_float2(v0, v1);
                }
            }
        }
    }
}

// ---------------- Combine ----------------
__global__ void __launch_bounds__(256) combine_kernel(float* __restrict__ out)
{
    int t = blockIdx.x;
    int p0 = g_tslot[2 * t], p1 = g_tslot[2 * t + 1];
    int i = threadIdx.x;
    float4 r = make_float4(0.f, 0.f, 0.f, 0.f);
    if (p0 >= 0) {
        float w = g_gates[p0];
        float4 a = ((const float4*)(g_y + (size_t)p0 * D_))[i];
        r.x += w * a.x; r.y += w * a.y; r.z += w * a.z; r.w += w * a.w;
    }
    if (p1 >= 0) {
        float w = g_gates[p1];
        float4 a = ((const float4*)(g_y + (size_t)p1 * D_))[i];
        r.x += w * a.x; r.y += w * a.y; r.z += w * a.z; r.w += w * a.w;
    }
    ((float4*)(out + (size_t)t * D_))[i] = r;
}

// ---------------- Load-balancing loss ----------------
__global__ void loss_kernel(float* __restrict__ loss_out)
{
    if (threadIdx.x == 0) {
        const float ideal = (float)T_ * TOPK_ / E_;
        float s = 0.f;
#pragma unroll
        for (int e = 0; e < E_; e++) {
            float d = (float)g_counts[e] - ideal;
            s += d * d;
        }
        *loss_out = s / ((float)T_ * (float)T_);
    }
}

// ---------------- Launch ----------------
extern "C" void kernel_launch(void* const* d_in, const int* in_sizes, int n_in,
                              void* d_out, int out_size)
{
    const float* x  = (const float*)d_in[0];
    const float* rw = (const float*)d_in[1];
    const float* w1 = (const float*)d_in[2];
    const float* b1 = (const float*)d_in[3];
    const float* w2 = (const float*)d_in[4];
    const float* b2 = (const float*)d_in[5];
    float* out = (float*)d_out;

    __nv_bfloat16 *xg2, *w1c, *w2c, *h2; float* y;
    cudaGetSymbolAddress((void**)&xg2, g_xg2);
    cudaGetSymbolAddress((void**)&w1c, g_w1c);
    cudaGetSymbolAddress((void**)&w2c, g_w2c);
    cudaGetSymbolAddress((void**)&h2,  g_h2);
    cudaGetSymbolAddress((void**)&y,   g_y);

    cudaFuncSetAttribute((const void*)gemm_mma_kernel<256, 4, 3, true>,
                         cudaFuncAttributeMaxDynamicSharedMemorySize, SMEM_BYTES_GEMM);
    cudaFuncSetAttribute((const void*)gemm_mma_kernel<256, 4, 3, false>,
                         cudaFuncAttributeMaxDynamicSharedMemorySize, SMEM_BYTES_GEMM);

    // Fork: weight conversions on a side stream. GEMM1 gates only on conv_w1;
    // conv_w2 overlaps GEMM1 and gates GEMM2.
    cudaStream_t s1;
    cudaEvent_t evRoot, evW1, evW2;
    cudaStreamCreateWithFlags(&s1, cudaStreamNonBlocking);
    cudaEventCreateWithFlags(&evRoot, cudaEventDisableTiming);
    cudaEventCreateWithFlags(&evW1, cudaEventDisableTiming);
    cudaEventCreateWithFlags(&evW2, cudaEventDisableTiming);

    cudaEventRecord(evRoot, 0);
    cudaStreamWaitEvent(s1, evRoot, 0);

    convert_w_kernel<<<dim3(DFF_ / 128, D_ / 32, E_), 256, 0, s1>>>(w1, w1c, D_, DFF_);
    cudaEventRecord(evW1, s1);
    convert_w_kernel<<<dim3(D_ / 128, DFF_ / 32, E_), 256, 0, s1>>>(w2, w2c, DFF_, D_);
    cudaEventRecord(evW2, s1);

    // Main stream: routing chain
    router_kernel<<<T_ / 8, 256>>>(x, rw);
    count_kernel<<<NCHK_, 256>>>();
    scan_init_kernel<<<1, 256>>>();
    place_kernel<<<NCHK_, 256>>>();
    gather_split_kernel<<<E_ * CAP_, 256>>>(x);

    cudaStreamWaitEvent(0, evW1, 0);
    gemm_mma_kernel<256, 4, 3, true><<<dim3(DFF_ / 256, CAP_ / 128, E_), 256, SMEM_BYTES_GEMM>>>(
        xg2, w1c, b1, (void*)h2, CAP_, DFF_, D_);

    cudaStreamWaitEvent(0, evW2, 0);
    gemm_mma_kernel<256, 4, 3, false><<<dim3(D_ / 256, CAP_ / 128, E_), 256, SMEM_BYTES_GEMM>>>(
        h2, w2c, b2, (void*)y, CAP_, D_, DFF_);

    combine_kernel<<<T_, 256>>>(out);
    loss_kernel<<<1, 32>>>(out + (out_size - 1));
}

// round 15
// speedup vs baseline: 2.1293x; 1.0338x over previous
#include <cuda_runtime.h>
#include <cuda_bf16.h>
#include <math.h>
#include <stdint.h>

// ---------------- Problem constants ----------------
#define B_    4
#define S_    2048
#define T_    8192          // B*S tokens
#define D_    1024          // d_model
#define DFF_  4096
#define E_    8
#define TOPK_ 2
#define CAP_  1024          // CAP_FACTOR * T / E

#define NCHK_ (T_ / 256)    // 32 dispatch chunks

#define G1_CTAS   1024      // 8 experts x (16 n-tiles x 8 m-tiles), tile 128x256
#define G2_CTAS   256       // 8 experts x (4 n-tiles x 8 m-tiles),  tile 128x256
#define ALL_CTAS  (G1_CTAS + G2_CTAS)

// Block-split storage: value = h + l, stored as [h-block | l-block] (2K per row).
// GEMM iterates 3 phases: (A=h,B=H), (A=h,B=L), (A=l,B=H)  == exact 3-term product.

// ---------------- Device scratch (static; no allocations allowed) ----------------
__device__ __nv_bfloat16 g_xg2[(size_t)E_ * CAP_ * 2 * D_];    // 33 MB  A of GEMM1 [h|l]
__device__ __nv_bfloat16 g_w1c[(size_t)E_ * DFF_ * 2 * D_];    // 134 MB B of GEMM1 [H|L]
__device__ __nv_bfloat16 g_w2c[(size_t)E_ * D_ * 2 * DFF_];    // 134 MB B of GEMM2 [H|L]
__device__ __nv_bfloat16 g_h2 [(size_t)E_ * CAP_ * 2 * DFF_];  // 134 MB A of GEMM2 [h|l]
__device__ float g_y[(size_t)E_ * CAP_ * D_];                  // expert outputs fp32
__device__ int   g_tokens[E_ * CAP_];
__device__ float g_gates [E_ * CAP_];
__device__ int   g_te0[T_], g_te1[T_];
__device__ float g_tw0[T_], g_tw1[T_];
__device__ int   g_tslot[2 * T_];
__device__ int   g_counts[E_];
__device__ int   g_ccnt[NCHK_][E_];
__device__ int   g_cofs[NCHK_][E_];
__device__ int   g_done[E_];      // GEMM1 completion counters (per expert)
__device__ int   g_w2done;        // conv_w2 completion flag

// ---------------- helpers ----------------
#define CP_ASYNC16(sa, ga) \
    asm volatile("cp.async.cg.shared.global [%0], [%1], 16;" :: "r"(sa), "l"(ga))
#define CP_COMMIT()  asm volatile("cp.async.commit_group;")
#define SWZ(o) ((o) ^ ((((uint32_t)(o)) >> 3) & 0x70))

#define LDMATRIX_X4(f, a) \
    asm volatile("ldmatrix.sync.aligned.m8n8.x4.shared.b16 {%0,%1,%2,%3}, [%4];" \
        : "=r"((f)[0]), "=r"((f)[1]), "=r"((f)[2]), "=r"((f)[3]) : "r"(a))

#define MMA_16816(c, a, b0, b1) \
    asm volatile("mma.sync.aligned.m16n8k16.row.col.f32.bf16.bf16.f32 " \
        "{%0,%1,%2,%3}, {%4,%5,%6,%7}, {%8,%9}, {%0,%1,%2,%3};" \
        : "+f"((c)[0]), "+f"((c)[1]), "+f"((c)[2]), "+f"((c)[3]) \
        : "r"((a)[0]), "r"((a)[1]), "r"((a)[2]), "r"((a)[3]), "r"(b0), "r"(b1))

// ---------------- Router ----------------
__global__ void __launch_bounds__(256) router_kernel(
    const float* __restrict__ x, const float* __restrict__ rw)
{
    __shared__ float srw[E_ * D_];
    int tid = threadIdx.x;
    for (int i = tid; i < E_ * D_; i += 256) srw[i] = rw[i];
    __syncthreads();

    int warp = tid >> 5, lane = tid & 31;
    int t = blockIdx.x * 8 + warp;
    const float* xt = x + (size_t)t * D_;

    float acc[E_];
#pragma unroll
    for (int e = 0; e < E_; e++) acc[e] = 0.f;
    for (int c = 0; c < D_ / 32; c++) {
        float xv = xt[c * 32 + lane];
#pragma unroll
        for (int e = 0; e < E_; e++)
            acc[e] += xv * srw[e * D_ + c * 32 + lane];
    }
#pragma unroll
    for (int e = 0; e < E_; e++) {
#pragma unroll
        for (int off = 16; off; off >>= 1)
            acc[e] += __shfl_xor_sync(0xffffffffu, acc[e], off);
    }
    if (lane == 0) {
        int b0 = 0; float v0 = acc[0];
#pragma unroll
        for (int e = 1; e < E_; e++) if (acc[e] > v0) { v0 = acc[e]; b0 = e; }
        int b1 = -1; float v1 = -INFINITY;
#pragma unroll
        for (int e = 0; e < E_; e++) if (e != b0 && acc[e] > v1) { v1 = acc[e]; b1 = e; }
        float ex = expf(v1 - v0);
        float w0 = 1.f / (1.f + ex);
        float w1 = ex * w0;
        g_te0[t] = b0; g_te1[t] = b1;
        g_tw0[t] = w0; g_tw1[t] = w1;
        g_tslot[2 * t + 0] = -1;
        g_tslot[2 * t + 1] = -1;
    }
}

// ---------------- Dispatch phase A: per-chunk per-expert counts ----------------
__global__ void __launch_bounds__(256) count_kernel()
{
    int tid = threadIdx.x;
    int t = blockIdx.x * 256 + tid;
    int lane = tid & 31, warp = tid >> 5;
    int e0 = g_te0[t], e1 = g_te1[t];
    __shared__ int wcnt[8][E_];
#pragma unroll
    for (int e = 0; e < E_; e++) {
        unsigned b = __ballot_sync(0xffffffffu, (e0 == e) || (e1 == e));
        if (lane == 0) wcnt[warp][e] = __popc(b);
    }
    __syncthreads();
    if (tid < E_) {
        int s = 0;
#pragma unroll
        for (int w = 0; w < 8; w++) s += wcnt[w][tid];
        g_ccnt[blockIdx.x][tid] = s;
    }
}

// ---------------- Dispatch phase B: chunk scan + pad-slot init + counter reset ----------------
__global__ void __launch_bounds__(256) scan_init_kernel()
{
    int tid = threadIdx.x;
    for (int i = tid; i < E_ * CAP_; i += 256) { g_tokens[i] = 0; g_gates[i] = 0.f; }
    if (tid < E_) {
        int run = 0;
#pragma unroll
        for (int b = 0; b < NCHK_; b++) {
            g_cofs[b][tid] = run;
            run += g_ccnt[b][tid];
        }
        g_counts[tid] = run;
        g_done[tid] = 0;
    }
}

// ---------------- Dispatch phase C: place tokens (token-order ranks) ----------------
__global__ void __launch_bounds__(256) place_kernel()
{
    int tid = threadIdx.x;
    int t = blockIdx.x * 256 + tid;
    int lane = tid & 31, warp = tid >> 5;
    int e0 = g_te0[t], e1 = g_te1[t];
    unsigned lt = (lane == 0) ? 0u : (0xffffffffu >> (32 - lane));
    __shared__ int ws[8];

#pragma unroll
    for (int e = 0; e < E_; e++) {
        bool f0 = (e0 == e), f1 = (e1 == e);
        bool f = f0 || f1;
        unsigned b = __ballot_sync(0xffffffffu, f);
        if (lane == 0) ws[warp] = __popc(b);
        __syncthreads();
        if (f) {
            int wpre = 0;
#pragma unroll
            for (int w = 0; w < 8; w++) if (w < warp) wpre += ws[w];
            int rank = wpre + __popc(b & lt);
            int slot = g_cofs[blockIdx.x][e] + rank;
            if (slot < CAP_) {
                g_tokens[e * CAP_ + slot] = t;
                g_gates [e * CAP_ + slot] = f0 ? g_tw0[t] : g_tw1[t];
                g_tslot[2 * t + (f0 ? 0 : 1)] = e * CAP_ + slot;
            }
        }
        __syncthreads();
    }
}

// ---------------- Gather + 2-block bf16 split: row = [h(D) | l(D)] ----------------
__global__ void __launch_bounds__(256) gather_split_kernel(const float* __restrict__ x)
{
    int row = blockIdx.x;                       // e*CAP + c
    int t = g_tokens[row];
    int tid = threadIdx.x;
    float4 v = ((const float4*)(x + (size_t)t * D_))[tid];
    float vv[4] = {v.x, v.y, v.z, v.w};
    unsigned short hs[4], ls[4];
#pragma unroll
    for (int j = 0; j < 4; j++) {
        __nv_bfloat16 hb = __float2bfloat16_rn(vv[j]);
        __nv_bfloat16 lb = __float2bfloat16_rn(vv[j] - __bfloat162float(hb));
        hs[j] = __bfloat16_as_ushort(hb);
        ls[j] = __bfloat16_as_ushort(lb);
    }
    __nv_bfloat16* base = g_xg2 + (size_t)row * 2 * D_;
    uint2 hv, lv;
    hv.x = (uint32_t)hs[0] | ((uint32_t)hs[1] << 16);
    hv.y = (uint32_t)hs[2] | ((uint32_t)hs[3] << 16);
    lv.x = (uint32_t)ls[0] | ((uint32_t)ls[1] << 16);
    lv.y = (uint32_t)ls[2] | ((uint32_t)ls[3] << 16);
    *(uint2*)(base + 4 * tid)      = hv;
    *(uint2*)(base + D_ + 4 * tid) = lv;
}

// ---------------- Flag helpers (side stream) ----------------
__global__ void clear_w2flag_kernel() { if (threadIdx.x == 0) g_w2done = 0; }
__global__ void set_w2flag_kernel()   { if (threadIdx.x == 0) { __threadfence(); g_w2done = 1; } }

// ---------------- Weight transpose + split: [E,K,N] fp32 -> [E,N,2K] bf16 [H|L] ----------------
__global__ void __launch_bounds__(256) convert_w_kernel(
    const float* __restrict__ src, __nv_bfloat16* __restrict__ dst, int K, int N)
{
    __shared__ float tile[32][129];
    int e = blockIdx.z;
    int k0 = blockIdx.y * 32, n0 = blockIdx.x * 128;
    int tid = threadIdx.x;
    const float* se = src + (size_t)e * K * N;
    __nv_bfloat16* de = dst + (size_t)e * N * 2 * K;

#pragma unroll
    for (int j = 0; j < 4; j++) {
        int idx = tid + j * 256;
        int r = idx >> 5, c4 = idx & 31;
        float4 v = *(const float4*)&se[(size_t)(k0 + r) * N + n0 + c4 * 4];
        float* tr = &tile[r][c4 * 4];
        tr[0] = v.x; tr[1] = v.y; tr[2] = v.z; tr[3] = v.w;
    }
    __syncthreads();

#pragma unroll
    for (int j = 0; j < 8; j++) {
        int task = tid + j * 256;
        int kp = task & 15;               // k-pair 0..15
        int nl = task >> 4;               // n 0..127
        int n = n0 + nl;
        float v0 = tile[2 * kp][nl];
        float v1 = tile[2 * kp + 1][nl];
        __nv_bfloat16 h0b = __float2bfloat16_rn(v0);
        __nv_bfloat16 l0b = __float2bfloat16_rn(v0 - __bfloat162float(h0b));
        __nv_bfloat16 h1b = __float2bfloat16_rn(v1);
        __nv_bfloat16 l1b = __float2bfloat16_rn(v1 - __bfloat162float(h1b));
        uint32_t h0 = __bfloat16_as_ushort(h0b), l0 = __bfloat16_as_ushort(l0b);
        uint32_t h1 = __bfloat16_as_ushort(h1b), l1 = __bfloat16_as_ushort(l1b);
        __nv_bfloat16* rowp = de + (size_t)n * 2 * K;
        *(uint32_t*)(rowp + (k0 + 2 * kp))     = h0 | (h1 << 16);   // H block
        *(uint32_t*)(rowp + K + (k0 + 2 * kp)) = l0 | (l1 << 16);   // L block
    }
}

// ---------------- Fused GEMM1+GEMM2: one 1280-CTA launch, device-side deps ----------------
// Blocks [0,1024): GEMM1 tiles (expert-major). Blocks [1024,1280): GEMM2 tiles.
// GEMM2 CTAs spin on g_w2done and g_done[e]==128 before loading. In-order block
// dispatch guarantees producers are resident before consumers spin.
__device__ __forceinline__ float gelu_exact(float v) {
    return 0.5f * v * (1.f + erff(v * 0.70710678118654752f));
}

#define SMEM_BYTES_GEMM (192 * 1024)
#define NSTAGE 4
#define PF 3

__global__ void __launch_bounds__(256, 1) fused_gemm_kernel(
    const __nv_bfloat16* __restrict__ xg2, const __nv_bfloat16* __restrict__ w1c,
    const __nv_bfloat16* __restrict__ w2c, __nv_bfloat16* __restrict__ h2,
    const float* __restrict__ b1, const float* __restrict__ b2,
    float* __restrict__ y)
{
    constexpr int BN = 256;
    constexpr int ABYTES = 128 * 128;
    constexpr int BBYTES = BN * 128;
    constexpr int STAGE  = ABYTES + BBYTES;
    constexpr int WCOLS  = BN / 4;   // 64
    constexpr int N8     = WCOLS / 8;
    constexpr int NTB    = (WCOLS + 15) / 16;

    extern __shared__ char smem[];
    uint32_t sb = (uint32_t)__cvta_generic_to_shared(smem);

    int tid  = threadIdx.x;
    int lane = tid & 31;
    int warp = tid >> 5;
    int wm = warp >> 2, wn = warp & 3;

    int bid = blockIdx.x;
    bool isG1 = (bid < G1_CTAS);

    int e, n0, m0, Ks, Nt;
    const __nv_bfloat16 *Ab, *Bb;
    const float* bias;
    if (isG1) {
        e  = bid >> 7;
        int r = bid & 127;
        n0 = (r & 15) * BN;  m0 = (r >> 4) * 128;
        Ks = D_;  Nt = DFF_;
        Ab = xg2 + (size_t)e * CAP_ * 2 * D_;
        Bb = w1c + (size_t)e * DFF_ * 2 * D_;
        bias = b1 + (size_t)e * DFF_;
    } else {
        int b2id = bid - G1_CTAS;
        e  = b2id >> 5;
        int r = b2id & 31;
        n0 = (r & 3) * BN;   m0 = (r >> 2) * 128;
        Ks = DFF_;  Nt = D_;
        Ab = h2  + (size_t)e * CAP_ * 2 * DFF_;
        Bb = w2c + (size_t)e * D_ * 2 * DFF_;
        bias = b2 + (size_t)e * D_;
        // Wait for conv_w2 and this expert's GEMM1 to complete.
        if (tid == 0) {
            while (atomicAdd(&g_w2done, 0) == 0) __nanosleep(200);
            while (atomicAdd(&g_done[e], 0) < 128) __nanosleep(200);
        }
        __syncthreads();
        __threadfence();
    }

    const int KC  = Ks >> 6;
    const int NCH = 3 * KC;
    const size_t ld = (size_t)Ks * 4;

    const char* Ae = (const char*)(Ab + (size_t)m0 * 2 * Ks);
    const char* Be = (const char*)(Bb + (size_t)n0 * 2 * Ks);

    auto chunk_off = [&](int c, int& aB, int& bB) {
        int phase = c / KC, idx = c - phase * KC;
        aB = ((phase == 2 ? KC + idx : idx)) * 128;   // l for phase 2, else h
        bB = ((phase == 1 ? KC + idx : idx)) * 128;   // L for phase 1, else H
    };

    auto load_stage = [&](int c, int s) {
        int aB, bB; chunk_off(c, aB, bB);
        const char* Ag = Ae + aB;
        const char* Bg = Be + bB;
        uint32_t Aoff = sb + s * STAGE;
        uint32_t Boff = Aoff + ABYTES;
#pragma unroll
        for (int i = 0; i < 4; i++) {
            int idx = tid + i * 256;
            int r = idx >> 3, c16 = idx & 7;
            CP_ASYNC16(Aoff + SWZ(r * 128 + c16 * 16), Ag + (size_t)r * ld + c16 * 16);
        }
#pragma unroll
        for (int i = 0; i < BN / 32; i++) {
            int idx = tid + i * 256;
            int r = idx >> 3, c16 = idx & 7;
            CP_ASYNC16(Boff + SWZ(r * 128 + c16 * 16), Bg + (size_t)r * ld + c16 * 16);
        }
    };

    float acc[4][N8][4];
#pragma unroll
    for (int i = 0; i < 4; i++)
#pragma unroll
        for (int j = 0; j < N8; j++)
#pragma unroll
            for (int k = 0; k < 4; k++) acc[i][j][k] = 0.f;

#pragma unroll
    for (int p = 0; p < PF; p++) { load_stage(p, p); CP_COMMIT(); }

    int aRow = wm * 64 + (lane & 15);
    int bRow = wn * WCOLS + (lane & 15);
    int halfCol = (lane >> 4) * 16;

    for (int c = 0; c < NCH; ++c) {
        asm volatile("cp.async.wait_group %0;" :: "n"(PF - 1));
        __syncthreads();
        if (c + PF < NCH) load_stage(c + PF, (c + PF) % NSTAGE);
        CP_COMMIT();

        int s = c % NSTAGE;
        uint32_t Aoff = sb + s * STAGE;
        uint32_t Boff = Aoff + ABYTES;

#pragma unroll
        for (int ks = 0; ks < 4; ks++) {
            uint32_t afr[4][4], bfr[NTB][4];
#pragma unroll
            for (int mt = 0; mt < 4; mt++) {
                uint32_t ad = Aoff + SWZ((aRow + mt * 16) * 128 + ks * 32 + halfCol);
                LDMATRIX_X4(afr[mt], ad);
            }
#pragma unroll
            for (int nt = 0; nt < NTB; nt++) {
                uint32_t bd = Boff + SWZ((bRow + nt * 16) * 128 + ks * 32 + halfCol);
                LDMATRIX_X4(bfr[nt], bd);
            }
#pragma unroll
            for (int mt = 0; mt < 4; mt++)
#pragma unroll
                for (int n8 = 0; n8 < N8; n8++) {
                    int nt = n8 >> 1, j = n8 & 1;
                    MMA_16816(acc[mt][n8], afr[mt], bfr[nt][j], bfr[nt][2 + j]);
                }
        }
    }

    // -------- Epilogue --------
#pragma unroll
    for (int mt = 0; mt < 4; mt++) {
#pragma unroll
        for (int rr = 0; rr < 2; rr++) {
            int row = m0 + wm * 64 + mt * 16 + (lane >> 2) + rr * 8;
#pragma unroll
            for (int n8 = 0; n8 < N8; n8++) {
                int colL = wn * WCOLS + n8 * 8 + (lane & 3) * 2;
                int col  = n0 + colL;
                float v0 = acc[mt][n8][rr * 2 + 0] + bias[col];
                float v1 = acc[mt][n8][rr * 2 + 1] + bias[col + 1];
                if (isG1) {
                    v0 = gelu_exact(v0); v1 = gelu_exact(v1);
                    __nv_bfloat16 h0b = __float2bfloat16_rn(v0);
                    __nv_bfloat16 l0b = __float2bfloat16_rn(v0 - __bfloat162float(h0b));
                    __nv_bfloat16 h1b = __float2bfloat16_rn(v1);
                    __nv_bfloat16 l1b = __float2bfloat16_rn(v1 - __bfloat162float(h1b));
                    uint32_t h0 = __bfloat16_as_ushort(h0b), l0 = __bfloat16_as_ushort(l0b);
                    uint32_t h1 = __bfloat16_as_ushort(h1b), l1 = __bfloat16_as_ushort(l1b);
                    __nv_bfloat16* rowp = h2 + (size_t)e * CAP_ * 2 * DFF_
                                             + (size_t)row * 2 * DFF_;
                    *(uint32_t*)(rowp + col)        = h0 | (h1 << 16);   // h block
                    *(uint32_t*)(rowp + DFF_ + col) = l0 | (l1 << 16);   // l block
                } else {
                    float* oe = y + (size_t)e * CAP_ * D_ + (size_t)row * D_ + col;
                    *(float2*)oe = make_float2(v0, v1);
                }
            }
        }
    }

    if (isG1) {
        __threadfence();
        __syncthreads();
        if (tid == 0) atomicAdd(&g_done[e], 1);
    }
}

// ---------------- Combine ----------------
__global__ void __launch_bounds__(256) combine_kernel(float* __restrict__ out)
{
    int t = blockIdx.x;
    int p0 = g_tslot[2 * t], p1 = g_tslot[2 * t + 1];
    int i = threadIdx.x;
    float4 r = make_float4(0.f, 0.f, 0.f, 0.f);
    if (p0 >= 0) {
        float w = g_gates[p0];
        float4 a = ((const float4*)(g_y + (size_t)p0 * D_))[i];
        r.x += w * a.x; r.y += w * a.y; r.z += w * a.z; r.w += w * a.w;
    }
    if (p1 >= 0) {
        float w = g_gates[p1];
        float4 a = ((const float4*)(g_y + (size_t)p1 * D_))[i];
        r.x += w * a.x; r.y += w * a.y; r.z += w * a.z; r.w += w * a.w;
    }
    ((float4*)(out + (size_t)t * D_))[i] = r;
}

// ---------------- Load-balancing loss ----------------
__global__ void loss_kernel(float* __restrict__ loss_out)
{
    if (threadIdx.x == 0) {
        const float ideal = (float)T_ * TOPK_ / E_;
        float s = 0.f;
#pragma unroll
        for (int e = 0; e < E_; e++) {
            float d = (float)g_counts[e] - ideal;
            s += d * d;
        }
        *loss_out = s / ((float)T_ * (float)T_);
    }
}

// ---------------- Launch ----------------
extern "C" void kernel_launch(void* const* d_in, const int* in_sizes, int n_in,
                              void* d_out, int out_size)
{
    const float* x  = (const float*)d_in[0];
    const float* rw = (const float*)d_in[1];
    const float* w1 = (const float*)d_in[2];
    const float* b1 = (const float*)d_in[3];
    const float* w2 = (const float*)d_in[4];
    const float* b2 = (const float*)d_in[5];
    float* out = (float*)d_out;

    __nv_bfloat16 *xg2, *w1c, *w2c, *h2; float* y;
    cudaGetSymbolAddress((void**)&xg2, g_xg2);
    cudaGetSymbolAddress((void**)&w1c, g_w1c);
    cudaGetSymbolAddress((void**)&w2c, g_w2c);
    cudaGetSymbolAddress((void**)&h2,  g_h2);
    cudaGetSymbolAddress((void**)&y,   g_y);

    cudaFuncSetAttribute((const void*)fused_gemm_kernel,
                         cudaFuncAttributeMaxDynamicSharedMemorySize, SMEM_BYTES_GEMM);

    // Side stream: clear w2 flag, conv_w1, conv_w2, set w2 flag (stream-ordered).
    cudaStream_t s1;
    cudaEvent_t evRoot, evW1, evSide;
    cudaStreamCreateWithFlags(&s1, cudaStreamNonBlocking);
    cudaEventCreateWithFlags(&evRoot, cudaEventDisableTiming);
    cudaEventCreateWithFlags(&evW1, cudaEventDisableTiming);
    cudaEventCreateWithFlags(&evSide, cudaEventDisableTiming);

    cudaEventRecord(evRoot, 0);
    cudaStreamWaitEvent(s1, evRoot, 0);

    clear_w2flag_kernel<<<1, 32, 0, s1>>>();
    convert_w_kernel<<<dim3(DFF_ / 128, D_ / 32, E_), 256, 0, s1>>>(w1, w1c, D_, DFF_);
    cudaEventRecord(evW1, s1);
    convert_w_kernel<<<dim3(D_ / 128, DFF_ / 32, E_), 256, 0, s1>>>(w2, w2c, DFF_, D_);
    set_w2flag_kernel<<<1, 32, 0, s1>>>();
    cudaEventRecord(evSide, s1);

    // Main stream: routing chain (scan_init also zeroes g_done)
    router_kernel<<<T_ / 8, 256>>>(x, rw);
    count_kernel<<<NCHK_, 256>>>();
    scan_init_kernel<<<1, 256>>>();
    place_kernel<<<NCHK_, 256>>>();
    gather_split_kernel<<<E_ * CAP_, 256>>>(x);

    // Fused GEMM launch gates only on conv_w1; GEMM2 CTAs gate on flags internally.
    cudaStreamWaitEvent(0, evW1, 0);
    fused_gemm_kernel<<<ALL_CTAS, 256, SMEM_BYTES_GEMM>>>(
        xg2, w1c, w2c, h2, b1, b2, y);

    // Join side stream back into the capture-origin stream (required by graph
    // capture). Semantically free: the side stream finished long ago.
    cudaStreamWaitEvent(0, evSide, 0);

    combine_kernel<<<T_, 256>>>(out);
    loss_kernel<<<1, 32>>>(out + (out_size - 1));
}

// round 16
// speedup vs baseline: 2.1402x; 1.0051x over previous
#include <cuda_runtime.h>
#include <cuda_bf16.h>
#include <math.h>
#include <stdint.h>

// ---------------- Problem constants ----------------
#define B_    4
#define S_    2048
#define T_    8192          // B*S tokens
#define D_    1024          // d_model
#define DFF_  4096
#define E_    8
#define TOPK_ 2
#define CAP_  1024          // CAP_FACTOR * T / E

#define NCHK_ (T_ / 256)    // 32 dispatch chunks

#define G1_CTAS   1024      // 8 experts x (8 m-blocks x 16 n-tiles), tile 128x256
#define G2_CTAS   256       // 8 experts x (8 m-blocks x 4 n-tiles),  tile 128x256
#define ALL_CTAS  (G1_CTAS + G2_CTAS)
#define MBLK_     8         // m-blocks per expert (CAP/128)

// Block-split storage: value = h + l, stored as [h-block | l-block] (2K per row).
// GEMM iterates 3 phases: (A=h,B=H), (A=h,B=L), (A=l,B=H)  == exact 3-term product.

// ---------------- Device scratch (static; no allocations allowed) ----------------
__device__ __nv_bfloat16 g_xg2[(size_t)E_ * CAP_ * 2 * D_];    // 33 MB  A of GEMM1 [h|l]
__device__ __nv_bfloat16 g_w1c[(size_t)E_ * DFF_ * 2 * D_];    // 134 MB B of GEMM1 [H|L]
__device__ __nv_bfloat16 g_w2c[(size_t)E_ * D_ * 2 * DFF_];    // 134 MB B of GEMM2 [H|L]
__device__ __nv_bfloat16 g_h2 [(size_t)E_ * CAP_ * 2 * DFF_];  // 134 MB A of GEMM2 [h|l]
__device__ float g_y[(size_t)E_ * CAP_ * D_];                  // expert outputs fp32
__device__ int   g_tokens[E_ * CAP_];
__device__ float g_gates [E_ * CAP_];
__device__ int   g_te0[T_], g_te1[T_];
__device__ float g_tw0[T_], g_tw1[T_];
__device__ int   g_tslot[2 * T_];
__device__ int   g_counts[E_];
__device__ int   g_ccnt[NCHK_][E_];
__device__ int   g_cofs[NCHK_][E_];
__device__ int   g_done[E_ * MBLK_];   // GEMM1 completion counters per (expert, m-block)
__device__ int   g_w2done;             // conv_w2 completion flag

// ---------------- helpers ----------------
#define CP_ASYNC16(sa, ga) \
    asm volatile("cp.async.cg.shared.global [%0], [%1], 16;" :: "r"(sa), "l"(ga))
#define CP_COMMIT()  asm volatile("cp.async.commit_group;")
#define SWZ(o) ((o) ^ ((((uint32_t)(o)) >> 3) & 0x70))

#define LDMATRIX_X4(f, a) \
    asm volatile("ldmatrix.sync.aligned.m8n8.x4.shared.b16 {%0,%1,%2,%3}, [%4];" \
        : "=r"((f)[0]), "=r"((f)[1]), "=r"((f)[2]), "=r"((f)[3]) : "r"(a))

#define MMA_16816(c, a, b0, b1) \
    asm volatile("mma.sync.aligned.m16n8k16.row.col.f32.bf16.bf16.f32 " \
        "{%0,%1,%2,%3}, {%4,%5,%6,%7}, {%8,%9}, {%0,%1,%2,%3};" \
        : "+f"((c)[0]), "+f"((c)[1]), "+f"((c)[2]), "+f"((c)[3]) \
        : "r"((a)[0]), "r"((a)[1]), "r"((a)[2]), "r"((a)[3]), "r"(b0), "r"(b1))

// ---------------- Router ----------------
__global__ void __launch_bounds__(256) router_kernel(
    const float* __restrict__ x, const float* __restrict__ rw)
{
    __shared__ float srw[E_ * D_];
    int tid = threadIdx.x;
    for (int i = tid; i < E_ * D_; i += 256) srw[i] = rw[i];
    __syncthreads();

    int warp = tid >> 5, lane = tid & 31;
    int t = blockIdx.x * 8 + warp;
    const float* xt = x + (size_t)t * D_;

    float acc[E_];
#pragma unroll
    for (int e = 0; e < E_; e++) acc[e] = 0.f;
    for (int c = 0; c < D_ / 32; c++) {
        float xv = xt[c * 32 + lane];
#pragma unroll
        for (int e = 0; e < E_; e++)
            acc[e] += xv * srw[e * D_ + c * 32 + lane];
    }
#pragma unroll
    for (int e = 0; e < E_; e++) {
#pragma unroll
        for (int off = 16; off; off >>= 1)
            acc[e] += __shfl_xor_sync(0xffffffffu, acc[e], off);
    }
    if (lane == 0) {
        int b0 = 0; float v0 = acc[0];
#pragma unroll
        for (int e = 1; e < E_; e++) if (acc[e] > v0) { v0 = acc[e]; b0 = e; }
        int b1 = -1; float v1 = -INFINITY;
#pragma unroll
        for (int e = 0; e < E_; e++) if (e != b0 && acc[e] > v1) { v1 = acc[e]; b1 = e; }
        float ex = expf(v1 - v0);
        float w0 = 1.f / (1.f + ex);
        float w1 = ex * w0;
        g_te0[t] = b0; g_te1[t] = b1;
        g_tw0[t] = w0; g_tw1[t] = w1;
        g_tslot[2 * t + 0] = -1;
        g_tslot[2 * t + 1] = -1;
    }
}

// ---------------- Dispatch phase A: per-chunk per-expert counts ----------------
__global__ void __launch_bounds__(256) count_kernel()
{
    int tid = threadIdx.x;
    int t = blockIdx.x * 256 + tid;
    int lane = tid & 31, warp = tid >> 5;
    int e0 = g_te0[t], e1 = g_te1[t];
    __shared__ int wcnt[8][E_];
#pragma unroll
    for (int e = 0; e < E_; e++) {
        unsigned b = __ballot_sync(0xffffffffu, (e0 == e) || (e1 == e));
        if (lane == 0) wcnt[warp][e] = __popc(b);
    }
    __syncthreads();
    if (tid < E_) {
        int s = 0;
#pragma unroll
        for (int w = 0; w < 8; w++) s += wcnt[w][tid];
        g_ccnt[blockIdx.x][tid] = s;
    }
}

// ---------------- Dispatch phase B: chunk scan + pad-slot init + counter reset ----------------
__global__ void __launch_bounds__(256) scan_init_kernel()
{
    int tid = threadIdx.x;
    for (int i = tid; i < E_ * CAP_; i += 256) { g_tokens[i] = 0; g_gates[i] = 0.f; }
    if (tid < E_ * MBLK_) g_done[tid] = 0;
    if (tid < E_) {
        int run = 0;
#pragma unroll
        for (int b = 0; b < NCHK_; b++) {
            g_cofs[b][tid] = run;
            run += g_ccnt[b][tid];
        }
        g_counts[tid] = run;
    }
}

// ---------------- Dispatch phase C: place tokens (token-order ranks) ----------------
__global__ void __launch_bounds__(256) place_kernel()
{
    int tid = threadIdx.x;
    int t = blockIdx.x * 256 + tid;
    int lane = tid & 31, warp = tid >> 5;
    int e0 = g_te0[t], e1 = g_te1[t];
    unsigned lt = (lane == 0) ? 0u : (0xffffffffu >> (32 - lane));
    __shared__ int ws[8];

#pragma unroll
    for (int e = 0; e < E_; e++) {
        bool f0 = (e0 == e), f1 = (e1 == e);
        bool f = f0 || f1;
        unsigned b = __ballot_sync(0xffffffffu, f);
        if (lane == 0) ws[warp] = __popc(b);
        __syncthreads();
        if (f) {
            int wpre = 0;
#pragma unroll
            for (int w = 0; w < 8; w++) if (w < warp) wpre += ws[w];
            int rank = wpre + __popc(b & lt);
            int slot = g_cofs[blockIdx.x][e] + rank;
            if (slot < CAP_) {
                g_tokens[e * CAP_ + slot] = t;
                g_gates [e * CAP_ + slot] = f0 ? g_tw0[t] : g_tw1[t];
                g_tslot[2 * t + (f0 ? 0 : 1)] = e * CAP_ + slot;
            }
        }
        __syncthreads();
    }
}

// ---------------- Gather + 2-block bf16 split: row = [h(D) | l(D)] ----------------
__global__ void __launch_bounds__(256) gather_split_kernel(const float* __restrict__ x)
{
    int row = blockIdx.x;                       // e*CAP + c
    int t = g_tokens[row];
    int tid = threadIdx.x;
    float4 v = ((const float4*)(x + (size_t)t * D_))[tid];
    float vv[4] = {v.x, v.y, v.z, v.w};
    unsigned short hs[4], ls[4];
#pragma unroll
    for (int j = 0; j < 4; j++) {
        __nv_bfloat16 hb = __float2bfloat16_rn(vv[j]);
        __nv_bfloat16 lb = __float2bfloat16_rn(vv[j] - __bfloat162float(hb));
        hs[j] = __bfloat16_as_ushort(hb);
        ls[j] = __bfloat16_as_ushort(lb);
    }
    __nv_bfloat16* base = g_xg2 + (size_t)row * 2 * D_;
    uint2 hv, lv;
    hv.x = (uint32_t)hs[0] | ((uint32_t)hs[1] << 16);
    hv.y = (uint32_t)hs[2] | ((uint32_t)hs[3] << 16);
    lv.x = (uint32_t)ls[0] | ((uint32_t)ls[1] << 16);
    lv.y = (uint32_t)ls[2] | ((uint32_t)ls[3] << 16);
    *(uint2*)(base + 4 * tid)      = hv;
    *(uint2*)(base + D_ + 4 * tid) = lv;
}

// ---------------- Flag helpers (side stream) ----------------
__global__ void clear_w2flag_kernel() { if (threadIdx.x == 0) g_w2done = 0; }
__global__ void set_w2flag_kernel()   { if (threadIdx.x == 0) { __threadfence(); g_w2done = 1; } }

// ---------------- Weight transpose + split: [E,K,N] fp32 -> [E,N,2K] bf16 [H|L] ----------------
__global__ void __launch_bounds__(256) convert_w_kernel(
    const float* __restrict__ src, __nv_bfloat16* __restrict__ dst, int K, int N)
{
    __shared__ float tile[32][129];
    int e = blockIdx.z;
    int k0 = blockIdx.y * 32, n0 = blockIdx.x * 128;
    int tid = threadIdx.x;
    const float* se = src + (size_t)e * K * N;
    __nv_bfloat16* de = dst + (size_t)e * N * 2 * K;

#pragma unroll
    for (int j = 0; j < 4; j++) {
        int idx = tid + j * 256;
        int r = idx >> 5, c4 = idx & 31;
        float4 v = *(const float4*)&se[(size_t)(k0 + r) * N + n0 + c4 * 4];
        float* tr = &tile[r][c4 * 4];
        tr[0] = v.x; tr[1] = v.y; tr[2] = v.z; tr[3] = v.w;
    }
    __syncthreads();

#pragma unroll
    for (int j = 0; j < 8; j++) {
        int task = tid + j * 256;
        int kp = task & 15;               // k-pair 0..15
        int nl = task >> 4;               // n 0..127
        int n = n0 + nl;
        float v0 = tile[2 * kp][nl];
        float v1 = tile[2 * kp + 1][nl];
        __nv_bfloat16 h0b = __float2bfloat16_rn(v0);
        __nv_bfloat16 l0b = __float2bfloat16_rn(v0 - __bfloat162float(h0b));
        __nv_bfloat16 h1b = __float2bfloat16_rn(v1);
        __nv_bfloat16 l1b = __float2bfloat16_rn(v1 - __bfloat162float(h1b));
        uint32_t h0 = __bfloat16_as_ushort(h0b), l0 = __bfloat16_as_ushort(l0b);
        uint32_t h1 = __bfloat16_as_ushort(h1b), l1 = __bfloat16_as_ushort(l1b);
        __nv_bfloat16* rowp = de + (size_t)n * 2 * K;
        *(uint32_t*)(rowp + (k0 + 2 * kp))     = h0 | (h1 << 16);   // H block
        *(uint32_t*)(rowp + K + (k0 + 2 * kp)) = l0 | (l1 << 16);   // L block
    }
}

// ---------------- Fused GEMM1+GEMM2: one 1280-CTA launch, device-side deps ----------------
// Blocks [0,1024): GEMM1 tiles (expert-major; n-tile fastest within an m-block).
// Blocks [1024,1280): GEMM2 tiles. A GEMM2 tile (e, mb) waits only on the 16
// GEMM1 producers sharing its (e, mb) — contiguous in dispatch order.
__device__ __forceinline__ float gelu_exact(float v) {
    return 0.5f * v * (1.f + erff(v * 0.70710678118654752f));
}

#define SMEM_BYTES_GEMM (192 * 1024)
#define NSTAGE 4
#define PF 3

__global__ void __launch_bounds__(256, 1) fused_gemm_kernel(
    const __nv_bfloat16* __restrict__ xg2, const __nv_bfloat16* __restrict__ w1c,
    const __nv_bfloat16* __restrict__ w2c, __nv_bfloat16* __restrict__ h2,
    const float* __restrict__ b1, const float* __restrict__ b2,
    float* __restrict__ y)
{
    constexpr int BN = 256;
    constexpr int ABYTES = 128 * 128;
    constexpr int BBYTES = BN * 128;
    constexpr int STAGE  = ABYTES + BBYTES;
    constexpr int WCOLS  = BN / 4;   // 64
    constexpr int N8     = WCOLS / 8;
    constexpr int NTB    = (WCOLS + 15) / 16;

    extern __shared__ char smem[];
    uint32_t sb = (uint32_t)__cvta_generic_to_shared(smem);

    int tid  = threadIdx.x;
    int lane = tid & 31;
    int warp = tid >> 5;
    int wm = warp >> 2, wn = warp & 3;

    int bid = blockIdx.x;
    bool isG1 = (bid < G1_CTAS);

    int e, n0, m0, Ks, Nt;
    const __nv_bfloat16 *Ab, *Bb;
    const float* bias;
    if (isG1) {
        e  = bid >> 7;
        int r = bid & 127;
        n0 = (r & 15) * BN;  m0 = (r >> 4) * 128;
        Ks = D_;  Nt = DFF_;
        Ab = xg2 + (size_t)e * CAP_ * 2 * D_;
        Bb = w1c + (size_t)e * DFF_ * 2 * D_;
        bias = b1 + (size_t)e * DFF_;
    } else {
        int b2id = bid - G1_CTAS;
        e  = b2id >> 5;
        int r = b2id & 31;
        n0 = (r & 3) * BN;   m0 = (r >> 2) * 128;
        Ks = DFF_;  Nt = D_;
        Ab = h2  + (size_t)e * CAP_ * 2 * DFF_;
        Bb = w2c + (size_t)e * D_ * 2 * DFF_;
        bias = b2 + (size_t)e * D_;
        // Wait for conv_w2 and the 16 GEMM1 producers of this (e, m-block).
        if (tid == 0) {
            int mb = m0 >> 7;
            while (atomicAdd(&g_w2done, 0) == 0) __nanosleep(200);
            while (atomicAdd(&g_done[e * MBLK_ + mb], 0) < 16) __nanosleep(200);
        }
        __syncthreads();
        __threadfence();
    }

    const int KC  = Ks >> 6;
    const int NCH = 3 * KC;
    const size_t ld = (size_t)Ks * 4;

    const char* Ae = (const char*)(Ab + (size_t)m0 * 2 * Ks);
    const char* Be = (const char*)(Bb + (size_t)n0 * 2 * Ks);

    auto chunk_off = [&](int c, int& aB, int& bB) {
        int phase = c / KC, idx = c - phase * KC;
        aB = ((phase == 2 ? KC + idx : idx)) * 128;   // l for phase 2, else h
        bB = ((phase == 1 ? KC + idx : idx)) * 128;   // L for phase 1, else H
    };

    auto load_stage = [&](int c, int s) {
        int aB, bB; chunk_off(c, aB, bB);
        const char* Ag = Ae + aB;
        const char* Bg = Be + bB;
        uint32_t Aoff = sb + s * STAGE;
        uint32_t Boff = Aoff + ABYTES;
#pragma unroll
        for (int i = 0; i < 4; i++) {
            int idx = tid + i * 256;
            int r = idx >> 3, c16 = idx & 7;
            CP_ASYNC16(Aoff + SWZ(r * 128 + c16 * 16), Ag + (size_t)r * ld + c16 * 16);
        }
#pragma unroll
        for (int i = 0; i < BN / 32; i++) {
            int idx = tid + i * 256;
            int r = idx >> 3, c16 = idx & 7;
            CP_ASYNC16(Boff + SWZ(r * 128 + c16 * 16), Bg + (size_t)r * ld + c16 * 16);
        }
    };

    float acc[4][N8][4];
#pragma unroll
    for (int i = 0; i < 4; i++)
#pragma unroll
        for (int j = 0; j < N8; j++)
#pragma unroll
            for (int k = 0; k < 4; k++) acc[i][j][k] = 0.f;

#pragma unroll
    for (int p = 0; p < PF; p++) { load_stage(p, p); CP_COMMIT(); }

    int aRow = wm * 64 + (lane & 15);
    int bRow = wn * WCOLS + (lane & 15);
    int halfCol = (lane >> 4) * 16;

    for (int c = 0; c < NCH; ++c) {
        asm volatile("cp.async.wait_group %0;" :: "n"(PF - 1));
        __syncthreads();
        if (c + PF < NCH) load_stage(c + PF, (c + PF) % NSTAGE);
        CP_COMMIT();

        int s = c % NSTAGE;
        uint32_t Aoff = sb + s * STAGE;
        uint32_t Boff = Aoff + ABYTES;

#pragma unroll
        for (int ks = 0; ks < 4; ks++) {
            uint32_t afr[4][4], bfr[NTB][4];
#pragma unroll
            for (int mt = 0; mt < 4; mt++) {
                uint32_t ad = Aoff + SWZ((aRow + mt * 16) * 128 + ks * 32 + halfCol);
                LDMATRIX_X4(afr[mt], ad);
            }
#pragma unroll
            for (int nt = 0; nt < NTB; nt++) {
                uint32_t bd = Boff + SWZ((bRow + nt * 16) * 128 + ks * 32 + halfCol);
                LDMATRIX_X4(bfr[nt], bd);
            }
#pragma unroll
            for (int mt = 0; mt < 4; mt++)
#pragma unroll
                for (int n8 = 0; n8 < N8; n8++) {
                    int nt = n8 >> 1, j = n8 & 1;
                    MMA_16816(acc[mt][n8], afr[mt], bfr[nt][j], bfr[nt][2 + j]);
                }
        }
    }

    // -------- Epilogue --------
#pragma unroll
    for (int mt = 0; mt < 4; mt++) {
#pragma unroll
        for (int rr = 0; rr < 2; rr++) {
            int row = m0 + wm * 64 + mt * 16 + (lane >> 2) + rr * 8;
#pragma unroll
            for (int n8 = 0; n8 < N8; n8++) {
                int colL = wn * WCOLS + n8 * 8 + (lane & 3) * 2;
                int col  = n0 + colL;
                float v0 = acc[mt][n8][rr * 2 + 0] + bias[col];
                float v1 = acc[mt][n8][rr * 2 + 1] + bias[col + 1];
                if (isG1) {
                    v0 = gelu_exact(v0); v1 = gelu_exact(v1);
                    __nv_bfloat16 h0b = __float2bfloat16_rn(v0);
                    __nv_bfloat16 l0b = __float2bfloat16_rn(v0 - __bfloat162float(h0b));
                    __nv_bfloat16 h1b = __float2bfloat16_rn(v1);
                    __nv_bfloat16 l1b = __float2bfloat16_rn(v1 - __bfloat162float(h1b));
                    uint32_t h0 = __bfloat16_as_ushort(h0b), l0 = __bfloat16_as_ushort(l0b);
                    uint32_t h1 = __bfloat16_as_ushort(h1b), l1 = __bfloat16_as_ushort(l1b);
                    __nv_bfloat16* rowp = h2 + (size_t)e * CAP_ * 2 * DFF_
                                             + (size_t)row * 2 * DFF_;
                    *(uint32_t*)(rowp + col)        = h0 | (h1 << 16);   // h block
                    *(uint32_t*)(rowp + DFF_ + col) = l0 | (l1 << 16);   // l block
                } else {
                    float* oe = y + (size_t)e * CAP_ * D_ + (size_t)row * D_ + col;
                    *(float2*)oe = make_float2(v0, v1);
                }
            }
        }
    }

    if (isG1) {
        __threadfence();
        __syncthreads();
        if (tid == 0) atomicAdd(&g_done[e * MBLK_ + (m0 >> 7)], 1);
    }
}

// ---------------- Combine ----------------
__global__ void __launch_bounds__(256) combine_kernel(float* __restrict__ out)
{
    int t = blockIdx.x;
    int p0 = g_tslot[2 * t], p1 = g_tslot[2 * t + 1];
    int i = threadIdx.x;
    float4 r = make_float4(0.f, 0.f, 0.f, 0.f);
    if (p0 >= 0) {
        float w = g_gates[p0];
        float4 a = ((const float4*)(g_y + (size_t)p0 * D_))[i];
        r.x += w * a.x; r.y += w * a.y; r.z += w * a.z; r.w += w * a.w;
    }
    if (p1 >= 0) {
        float w = g_gates[p1];
        float4 a = ((const float4*)(g_y + (size_t)p1 * D_))[i];
        r.x += w * a.x; r.y += w * a.y; r.z += w * a.z; r.w += w * a.w;
    }
    ((float4*)(out + (size_t)t * D_))[i] = r;
}

// ---------------- Load-balancing loss ----------------
__global__ void loss_kernel(float* __restrict__ loss_out)
{
    if (threadIdx.x == 0) {
        const float ideal = (float)T_ * TOPK_ / E_;
        float s = 0.f;
#pragma unroll
        for (int e = 0; e < E_; e++) {
            float d = (float)g_counts[e] - ideal;
            s += d * d;
        }
        *loss_out = s / ((float)T_ * (float)T_);
    }
}

// ---------------- Launch ----------------
extern "C" void kernel_launch(void* const* d_in, const int* in_sizes, int n_in,
                              void* d_out, int out_size)
{
    const float* x  = (const float*)d_in[0];
    const float* rw = (const float*)d_in[1];
    const float* w1 = (const float*)d_in[2];
    const float* b1 = (const float*)d_in[3];
    const float* w2 = (const float*)d_in[4];
    const float* b2 = (const float*)d_in[5];
    float* out = (float*)d_out;

    __nv_bfloat16 *xg2, *w1c, *w2c, *h2; float* y;
    cudaGetSymbolAddress((void**)&xg2, g_xg2);
    cudaGetSymbolAddress((void**)&w1c, g_w1c);
    cudaGetSymbolAddress((void**)&w2c, g_w2c);
    cudaGetSymbolAddress((void**)&h2,  g_h2);
    cudaGetSymbolAddress((void**)&y,   g_y);

    cudaFuncSetAttribute((const void*)fused_gemm_kernel,
                         cudaFuncAttributeMaxDynamicSharedMemorySize, SMEM_BYTES_GEMM);

    // Side stream: clear w2 flag, conv_w1, conv_w2, set w2 flag (stream-ordered).
    cudaStream_t s1;
    cudaEvent_t evRoot, evW1, evSide;
    cudaStreamCreateWithFlags(&s1, cudaStreamNonBlocking);
    cudaEventCreateWithFlags(&evRoot, cudaEventDisableTiming);
    cudaEventCreateWithFlags(&evW1, cudaEventDisableTiming);
    cudaEventCreateWithFlags(&evSide, cudaEventDisableTiming);

    cudaEventRecord(evRoot, 0);
    cudaStreamWaitEvent(s1, evRoot, 0);

    clear_w2flag_kernel<<<1, 32, 0, s1>>>();
    convert_w_kernel<<<dim3(DFF_ / 128, D_ / 32, E_), 256, 0, s1>>>(w1, w1c, D_, DFF_);
    cudaEventRecord(evW1, s1);
    convert_w_kernel<<<dim3(D_ / 128, DFF_ / 32, E_), 256, 0, s1>>>(w2, w2c, DFF_, D_);
    set_w2flag_kernel<<<1, 32, 0, s1>>>();
    cudaEventRecord(evSide, s1);

    // Main stream: routing chain (scan_init also zeroes g_done)
    router_kernel<<<T_ / 8, 256>>>(x, rw);
    count_kernel<<<NCHK_, 256>>>();
    scan_init_kernel<<<1, 256>>>();
    place_kernel<<<NCHK_, 256>>>();
    gather_split_kernel<<<E_ * CAP_, 256>>>(x);

    // Fused GEMM launch gates only on conv_w1; GEMM2 CTAs gate on flags internally.
    cudaStreamWaitEvent(0, evW1, 0);
    fused_gemm_kernel<<<ALL_CTAS, 256, SMEM_BYTES_GEMM>>>(
        xg2, w1c, w2c, h2, b1, b2, y);

    // Join side stream back into the capture-origin stream (required by graph
    // capture). Semantically free: the side stream finished long ago.
    cudaStreamWaitEvent(0, evSide, 0);

    combine_kernel<<<T_, 256>>>(out);
    loss_kernel<<<1, 32>>>(out + (out_size - 1));
}